// round 1
// baseline (speedup 1.0000x reference)
#include <cuda_runtime.h>

// Problem constants
#define BATCH 8
#define SEQ   2048
#define DIM   512

// GEMM tiling
#define BM 128
#define BN 128
#define BK 8

// Scratch (device globals: allocation-free per harness rules)
__device__ float g_Q[(long)BATCH * SEQ * DIM];          // 32 MB
__device__ float g_K[(long)BATCH * SEQ * DIM];          // 32 MB
__device__ float g_V[(long)BATCH * SEQ * DIM];          // 32 MB
__device__ float g_S[(long)BATCH * SEQ * SEQ];          // 128 MB

// C[M,N] = alpha * A[M,K] @ B            (TRANSB=false: B is [K,N] row-major)
//                                         (TRANSB=true:  B is [N,K] row-major, dot over K)
// Batched via blockIdx.z with element strides sA/sB/sC. All dims multiples of tile sizes.
template <bool TRANSB>
__global__ __launch_bounds__(256)
void gemm_kernel(const float* __restrict__ A, const float* __restrict__ B,
                 float* __restrict__ C,
                 int M, int N, int K,
                 long sA, long sB, long sC, float alpha)
{
    __shared__ float As[BK][BM];
    __shared__ float Bs[BK][BN];

    const float* Ab = A + (long)blockIdx.z * sA;
    const float* Bb = B + (long)blockIdx.z * sB;
    float*       Cb = C + (long)blockIdx.z * sC;

    const int tid = threadIdx.x;
    const int tx  = tid & 15;        // 0..15 -> col micro-tile
    const int ty  = tid >> 4;        // 0..15 -> row micro-tile
    const int rowBase = blockIdx.y * BM;
    const int colBase = blockIdx.x * BN;

    // Loader indices
    const int arow = tid >> 1;        // 0..127
    const int acol = (tid & 1) * 4;   // 0 or 4
    const int brow = tid >> 5;        // 0..7   (non-trans B)
    const int bcol = (tid & 31) * 4;  // 0..124

    float acc[8][8];
#pragma unroll
    for (int i = 0; i < 8; i++)
#pragma unroll
        for (int j = 0; j < 8; j++) acc[i][j] = 0.0f;

    for (int kb = 0; kb < K; kb += BK) {
        // Load A tile 128x8 (transpose into As[k][m])
        {
            float4 v = *reinterpret_cast<const float4*>(
                &Ab[(long)(rowBase + arow) * K + kb + acol]);
            As[acol + 0][arow] = v.x;
            As[acol + 1][arow] = v.y;
            As[acol + 2][arow] = v.z;
            As[acol + 3][arow] = v.w;
        }
        if (TRANSB) {
            // B is [N,K]: load 128 n-rows x 8 k-cols, transpose into Bs[k][n]
            float4 v = *reinterpret_cast<const float4*>(
                &Bb[(long)(colBase + arow) * K + kb + acol]);
            Bs[acol + 0][arow] = v.x;
            Bs[acol + 1][arow] = v.y;
            Bs[acol + 2][arow] = v.z;
            Bs[acol + 3][arow] = v.w;
        } else {
            // B is [K,N]: load 8 k-rows x 128 n-cols directly
            float4 v = *reinterpret_cast<const float4*>(
                &Bb[(long)(kb + brow) * N + colBase + bcol]);
            *reinterpret_cast<float4*>(&Bs[brow][bcol]) = v;
        }
        __syncthreads();

#pragma unroll
        for (int kk = 0; kk < BK; kk++) {
            float4 a0 = *reinterpret_cast<const float4*>(&As[kk][ty * 8]);
            float4 a1 = *reinterpret_cast<const float4*>(&As[kk][ty * 8 + 4]);
            float4 b0 = *reinterpret_cast<const float4*>(&Bs[kk][tx * 8]);
            float4 b1 = *reinterpret_cast<const float4*>(&Bs[kk][tx * 8 + 4]);
            float a[8] = {a0.x, a0.y, a0.z, a0.w, a1.x, a1.y, a1.z, a1.w};
            float b[8] = {b0.x, b0.y, b0.z, b0.w, b1.x, b1.y, b1.z, b1.w};
#pragma unroll
            for (int i = 0; i < 8; i++)
#pragma unroll
                for (int j = 0; j < 8; j++)
                    acc[i][j] = fmaf(a[i], b[j], acc[i][j]);
        }
        __syncthreads();
    }

#pragma unroll
    for (int i = 0; i < 8; i++) {
        long r = (long)(rowBase + ty * 8 + i);
        float4 o0, o1;
        o0.x = acc[i][0] * alpha; o0.y = acc[i][1] * alpha;
        o0.z = acc[i][2] * alpha; o0.w = acc[i][3] * alpha;
        o1.x = acc[i][4] * alpha; o1.y = acc[i][5] * alpha;
        o1.z = acc[i][6] * alpha; o1.w = acc[i][7] * alpha;
        *reinterpret_cast<float4*>(&Cb[r * N + colBase + tx * 8])     = o0;
        *reinterpret_cast<float4*>(&Cb[r * N + colBase + tx * 8 + 4]) = o1;
    }
}

// Row softmax over SEQ=2048 columns. One CTA (256 threads) per row, 8 elems/thread.
__global__ __launch_bounds__(256)
void softmax_kernel(float* __restrict__ S)
{
    float* p = S + (long)blockIdx.x * SEQ;
    const int tid  = threadIdx.x;
    const int lane = tid & 31;
    const int warp = tid >> 5;
    __shared__ float red[8];

    float4 u0 = *reinterpret_cast<const float4*>(&p[tid * 8]);
    float4 u1 = *reinterpret_cast<const float4*>(&p[tid * 8 + 4]);
    float v[8] = {u0.x, u0.y, u0.z, u0.w, u1.x, u1.y, u1.z, u1.w};

    float m = v[0];
#pragma unroll
    for (int i = 1; i < 8; i++) m = fmaxf(m, v[i]);
#pragma unroll
    for (int o = 16; o > 0; o >>= 1) m = fmaxf(m, __shfl_xor_sync(0xffffffffu, m, o));
    if (lane == 0) red[warp] = m;
    __syncthreads();
    m = red[0];
#pragma unroll
    for (int i = 1; i < 8; i++) m = fmaxf(m, red[i]);
    __syncthreads();

    float s = 0.0f;
#pragma unroll
    for (int i = 0; i < 8; i++) { v[i] = __expf(v[i] - m); s += v[i]; }
#pragma unroll
    for (int o = 16; o > 0; o >>= 1) s += __shfl_xor_sync(0xffffffffu, s, o);
    if (lane == 0) red[warp] = s;
    __syncthreads();
    s = red[0];
#pragma unroll
    for (int i = 1; i < 8; i++) s += red[i];

    float inv = __frcp_rn(s);
    float4 w0, w1;
    w0.x = v[0] * inv; w0.y = v[1] * inv; w0.z = v[2] * inv; w0.w = v[3] * inv;
    w1.x = v[4] * inv; w1.y = v[5] * inv; w1.z = v[6] * inv; w1.w = v[7] * inv;
    *reinterpret_cast<float4*>(&p[tid * 8])     = w0;
    *reinterpret_cast<float4*>(&p[tid * 8 + 4]) = w1;
}

extern "C" void kernel_launch(void* const* d_in, const int* in_sizes, int n_in,
                              void* d_out, int out_size)
{
    const float* x  = (const float*)d_in[0];
    const float* Wq = (const float*)d_in[1];
    const float* Wk = (const float*)d_in[2];
    const float* Wv = (const float*)d_in[3];
    float* out = (float*)d_out;

    float *Q, *K, *V, *S;
    cudaGetSymbolAddress((void**)&Q, g_Q);
    cudaGetSymbolAddress((void**)&K, g_K);
    cudaGetSymbolAddress((void**)&V, g_V);
    cudaGetSymbolAddress((void**)&S, g_S);

    const dim3 blk(256);
    const int M_proj = BATCH * SEQ;  // 16384

    // Q/K/V projections: [16384,512] @ [512,512]
    dim3 gp(DIM / BN, M_proj / BM, 1);
    gemm_kernel<false><<<gp, blk>>>(x, Wq, Q, M_proj, DIM, DIM, 0, 0, 0, 1.0f);
    gemm_kernel<false><<<gp, blk>>>(x, Wk, K, M_proj, DIM, DIM, 0, 0, 0, 1.0f);
    gemm_kernel<false><<<gp, blk>>>(x, Wv, V, M_proj, DIM, DIM, 0, 0, 0, 1.0f);

    // scores = Q @ K^T / sqrt(D), per batch
    const float scale = 0.044194173824159216f;  // 1/sqrt(512)
    dim3 gs(SEQ / BN, SEQ / BM, BATCH);
    gemm_kernel<true><<<gs, blk>>>(Q, K, S, SEQ, SEQ, DIM,
                                   (long)SEQ * DIM, (long)SEQ * DIM,
                                   (long)SEQ * SEQ, scale);

    // softmax rows
    softmax_kernel<<<BATCH * SEQ, blk>>>(S);

    // out = A @ V, per batch
    dim3 go(DIM / BN, SEQ / BM, BATCH);
    gemm_kernel<false><<<go, blk>>>(S, V, out, SEQ, DIM, SEQ,
                                    (long)SEQ * SEQ, (long)SEQ * DIM,
                                    (long)SEQ * DIM, 1.0f);
}

// round 3
// speedup vs baseline: 2.5607x; 2.5607x over previous
#include <cuda_runtime.h>
#include <cuda_bf16.h>
#include <cstdint>

// Problem constants
#define BATCH 8
#define SEQ   2048
#define DIM   512

// ---------------------------------------------------------------------------
// Scratch (device globals: allocation-free per harness rules)
// ---------------------------------------------------------------------------
__device__ float g_Q [(long)BATCH * SEQ * DIM];   // 32 MB
__device__ float g_K [(long)BATCH * SEQ * DIM];   // 32 MB
__device__ float g_V [(long)BATCH * SEQ * DIM];   // 32 MB
__device__ float g_Vt[(long)BATCH * SEQ * DIM];   // 32 MB (V transposed per batch)
__device__ float g_S [(long)BATCH * SEQ * SEQ];   // 128 MB (scores / probs)
__device__ float g_WT[3L * DIM * DIM];            // 3 MB   (Wq^T, Wk^T, Wv^T)

// ---------------------------------------------------------------------------
// PTX helpers (baseline ISA only: ldmatrix + mma.sync, sm_80+)
// ---------------------------------------------------------------------------
__device__ __forceinline__ uint32_t smem_u32(const void* p) {
    uint32_t a;
    asm("{ .reg .u64 t; cvta.to.shared.u64 t, %1; cvt.u32.u64 %0, t; }"
        : "=r"(a) : "l"(p));
    return a;
}

__device__ __forceinline__ void ldsm_x4(uint32_t addr, uint32_t* r) {
    asm volatile("ldmatrix.sync.aligned.m8n8.x4.shared.b16 {%0,%1,%2,%3}, [%4];"
                 : "=r"(r[0]), "=r"(r[1]), "=r"(r[2]), "=r"(r[3]) : "r"(addr));
}

__device__ __forceinline__ void mma_bf16(float* c, const uint32_t* a, const uint32_t* b) {
    asm volatile(
        "mma.sync.aligned.m16n8k16.row.col.f32.bf16.bf16.f32 "
        "{%0,%1,%2,%3}, {%4,%5,%6,%7}, {%8,%9}, {%0,%1,%2,%3};"
        : "+f"(c[0]), "+f"(c[1]), "+f"(c[2]), "+f"(c[3])
        : "r"(a[0]), "r"(a[1]), "r"(a[2]), "r"(a[3]), "r"(b[0]), "r"(b[1]));
}

// Convert float4 -> hi/lo bf16 pairs and store 8B each to smem
__device__ __forceinline__ void cvt_store(char* hi, char* lo, uint32_t off, float4 v) {
    __nv_bfloat162 h01 = __floats2bfloat162_rn(v.x, v.y);
    __nv_bfloat162 h23 = __floats2bfloat162_rn(v.z, v.w);
    __nv_bfloat162 l01 = __floats2bfloat162_rn(v.x - __bfloat162float(h01.x),
                                               v.y - __bfloat162float(h01.y));
    __nv_bfloat162 l23 = __floats2bfloat162_rn(v.z - __bfloat162float(h23.x),
                                               v.w - __bfloat162float(h23.y));
    *reinterpret_cast<uint2*>(hi + off) =
        make_uint2(*reinterpret_cast<uint32_t*>(&h01), *reinterpret_cast<uint32_t*>(&h23));
    *reinterpret_cast<uint2*>(lo + off) =
        make_uint2(*reinterpret_cast<uint32_t*>(&l01), *reinterpret_cast<uint32_t*>(&l23));
}

// ---------------------------------------------------------------------------
// Tensor-core GEMM (warp-level HMMA): C[M,N] = alpha * A[M,K] @ B[N,K]^T
// Both A and B K-major fp32. Split precision: x = hi + lo (bf16);
// acc += Ahi*Bhi + Ahi*Blo + Alo*Bhi in fp32.
// CTA tile 128x128, K-chunk 32 fp32. 8 warps, each 64x32.
// SMEM rows padded to 40 bf16 (80B) -> conflict-free ldmatrix.
// ---------------------------------------------------------------------------
#define BKF 32
#define ROWB 80   // bytes per smem row (40 bf16)

__global__ __launch_bounds__(256, 1)
void tc_gemm_kernel(const float* __restrict__ A, const float* __restrict__ B,
                    float* __restrict__ C, int M, int N, int K,
                    long sA, long sB, long sC, float alpha)
{
    __shared__ __align__(16) char sAhi[128 * ROWB];
    __shared__ __align__(16) char sAlo[128 * ROWB];
    __shared__ __align__(16) char sBhi[128 * ROWB];
    __shared__ __align__(16) char sBlo[128 * ROWB];

    const float* Ab = A + (long)blockIdx.z * sA;
    const float* Bb = B + (long)blockIdx.z * sB;
    float*       Cb = C + (long)blockIdx.z * sC;

    const int tid  = threadIdx.x;
    const int wid  = tid >> 5;
    const int lane = tid & 31;
    const int wm   = wid & 1;   // 2 warps along M (64 rows each)
    const int wn   = wid >> 1;  // 4 warps along N (32 cols each)

    const int rowA = blockIdx.y * 128;
    const int rowB = blockIdx.x * 128;

    // ldmatrix per-lane selectors
    const int aRow = lane & 15;                          // A: row within 16
    const int aK   = (lane >> 4) * 8;                    // A: k-half
    const int bRow = (lane & 7) + ((lane >> 4) & 1) * 8; // B: n row within 16
    const int bK   = ((lane >> 3) & 1) * 8;              // B: k-half

    const uint32_t uAhi = smem_u32(sAhi), uAlo = smem_u32(sAlo);
    const uint32_t uBhi = smem_u32(sBhi), uBlo = smem_u32(sBlo);

    // Loader mapping: idx = tid + 256*i ; row = idx>>3, c4 = idx&7
    const int lrow = tid >> 3;        // 0..31 (advance by 32 rows per i)
    const int lc4  = tid & 7;         // float4 index within 32-float row

    float acc[4][4][4];
#pragma unroll
    for (int i = 0; i < 4; i++)
#pragma unroll
        for (int j = 0; j < 4; j++)
#pragma unroll
            for (int k = 0; k < 4; k++) acc[i][j][k] = 0.0f;

    const int nchunk = K / BKF;

    // Prefetch chunk 0
    float4 sa[4], sb[4];
#pragma unroll
    for (int i = 0; i < 4; i++) {
        const int r = lrow + i * 32;
        sa[i] = *reinterpret_cast<const float4*>(&Ab[(long)(rowA + r) * K + lc4 * 4]);
        sb[i] = *reinterpret_cast<const float4*>(&Bb[(long)(rowB + r) * K + lc4 * 4]);
    }

    for (int c = 0; c < nchunk; c++) {
        // Store staged chunk to smem (hi/lo split)
#pragma unroll
        for (int i = 0; i < 4; i++) {
            const int r = lrow + i * 32;
            const uint32_t off = (uint32_t)(r * ROWB + lc4 * 8);
            cvt_store(sAhi, sAlo, off, sa[i]);
            cvt_store(sBhi, sBlo, off, sb[i]);
        }
        __syncthreads();

        // Prefetch next chunk (overlaps with MMA below)
        if (c + 1 < nchunk) {
            const long kb = (long)(c + 1) * BKF;
#pragma unroll
            for (int i = 0; i < 4; i++) {
                const int r = lrow + i * 32;
                sa[i] = *reinterpret_cast<const float4*>(&Ab[(long)(rowA + r) * K + kb + lc4 * 4]);
                sb[i] = *reinterpret_cast<const float4*>(&Bb[(long)(rowB + r) * K + kb + lc4 * 4]);
            }
        }

        // Compute: 2 k-steps of 16
#pragma unroll
        for (int ks = 0; ks < 2; ks++) {
            uint32_t ah[4][4], al[4][4], bh[4][2], bl[4][2];
#pragma unroll
            for (int mi = 0; mi < 4; mi++) {
                const uint32_t off = (uint32_t)((wm * 64 + mi * 16 + aRow) * ROWB
                                                + (ks * 16 + aK) * 2);
                ldsm_x4(uAhi + off, ah[mi]);
                ldsm_x4(uAlo + off, al[mi]);
            }
#pragma unroll
            for (int nj = 0; nj < 2; nj++) {
                const uint32_t off = (uint32_t)((wn * 32 + nj * 16 + bRow) * ROWB
                                                + (ks * 16 + bK) * 2);
                uint32_t rh[4], rl[4];
                ldsm_x4(uBhi + off, rh);
                ldsm_x4(uBlo + off, rl);
                bh[nj * 2][0] = rh[0]; bh[nj * 2][1] = rh[1];
                bh[nj * 2 + 1][0] = rh[2]; bh[nj * 2 + 1][1] = rh[3];
                bl[nj * 2][0] = rl[0]; bl[nj * 2][1] = rl[1];
                bl[nj * 2 + 1][0] = rl[2]; bl[nj * 2 + 1][1] = rl[3];
            }
#pragma unroll
            for (int mi = 0; mi < 4; mi++)
#pragma unroll
                for (int ni = 0; ni < 4; ni++) {
                    mma_bf16(acc[mi][ni], ah[mi], bh[ni]);
                    mma_bf16(acc[mi][ni], ah[mi], bl[ni]);
                    mma_bf16(acc[mi][ni], al[mi], bh[ni]);
                }
        }
        __syncthreads();
    }

    // Epilogue
    const int g = lane >> 2, t = lane & 3;
#pragma unroll
    for (int mi = 0; mi < 4; mi++) {
        const long r0 = (long)(rowA + wm * 64 + mi * 16 + g);
#pragma unroll
        for (int ni = 0; ni < 4; ni++) {
            const int col = rowB + wn * 32 + ni * 8 + t * 2;
            float2 v0 = make_float2(acc[mi][ni][0] * alpha, acc[mi][ni][1] * alpha);
            float2 v1 = make_float2(acc[mi][ni][2] * alpha, acc[mi][ni][3] * alpha);
            *reinterpret_cast<float2*>(&Cb[r0 * N + col])       = v0;
            *reinterpret_cast<float2*>(&Cb[(r0 + 8) * N + col]) = v1;
        }
    }
}

// ---------------------------------------------------------------------------
// Transpose: out[c,r] = in[r,c], R x C both multiples of 32, batched via z
// ---------------------------------------------------------------------------
__global__ __launch_bounds__(256)
void transpose_kernel(const float* __restrict__ in, float* __restrict__ out,
                      int R, int C, long sIn, long sOut)
{
    __shared__ float t[32][33];
    in  += (long)blockIdx.z * sIn;
    out += (long)blockIdx.z * sOut;
    const int rb = blockIdx.y * 32, cb = blockIdx.x * 32;
    const int x = threadIdx.x, y = threadIdx.y;  // 32 x 8
#pragma unroll
    for (int j = 0; j < 32; j += 8)
        t[y + j][x] = in[(long)(rb + y + j) * C + cb + x];
    __syncthreads();
#pragma unroll
    for (int j = 0; j < 32; j += 8)
        out[(long)(cb + y + j) * R + rb + x] = t[x][y + j];
}

// ---------------------------------------------------------------------------
// Row softmax over SEQ=2048 columns. One CTA (256 threads) per row.
// ---------------------------------------------------------------------------
__global__ __launch_bounds__(256)
void softmax_kernel(float* __restrict__ S)
{
    float* p = S + (long)blockIdx.x * SEQ;
    const int tid  = threadIdx.x;
    const int lane = tid & 31;
    const int warp = tid >> 5;
    __shared__ float red[8];

    float4 u0 = *reinterpret_cast<const float4*>(&p[tid * 8]);
    float4 u1 = *reinterpret_cast<const float4*>(&p[tid * 8 + 4]);
    float v[8] = {u0.x, u0.y, u0.z, u0.w, u1.x, u1.y, u1.z, u1.w};

    float m = v[0];
#pragma unroll
    for (int i = 1; i < 8; i++) m = fmaxf(m, v[i]);
#pragma unroll
    for (int o = 16; o > 0; o >>= 1) m = fmaxf(m, __shfl_xor_sync(0xffffffffu, m, o));
    if (lane == 0) red[warp] = m;
    __syncthreads();
    m = red[0];
#pragma unroll
    for (int i = 1; i < 8; i++) m = fmaxf(m, red[i]);
    __syncthreads();

    float s = 0.0f;
#pragma unroll
    for (int i = 0; i < 8; i++) { v[i] = __expf(v[i] - m); s += v[i]; }
#pragma unroll
    for (int o = 16; o > 0; o >>= 1) s += __shfl_xor_sync(0xffffffffu, s, o);
    if (lane == 0) red[warp] = s;
    __syncthreads();
    s = red[0];
#pragma unroll
    for (int i = 1; i < 8; i++) s += red[i];

    float inv = __frcp_rn(s);
    float4 w0, w1;
    w0.x = v[0] * inv; w0.y = v[1] * inv; w0.z = v[2] * inv; w0.w = v[3] * inv;
    w1.x = v[4] * inv; w1.y = v[5] * inv; w1.z = v[6] * inv; w1.w = v[7] * inv;
    *reinterpret_cast<float4*>(&p[tid * 8])     = w0;
    *reinterpret_cast<float4*>(&p[tid * 8 + 4]) = w1;
}

// ---------------------------------------------------------------------------
extern "C" void kernel_launch(void* const* d_in, const int* in_sizes, int n_in,
                              void* d_out, int out_size)
{
    const float* x  = (const float*)d_in[0];
    const float* Wq = (const float*)d_in[1];
    const float* Wk = (const float*)d_in[2];
    const float* Wv = (const float*)d_in[3];
    float* out = (float*)d_out;

    float *Q, *K, *V, *Vt, *S, *WT;
    cudaGetSymbolAddress((void**)&Q,  g_Q);
    cudaGetSymbolAddress((void**)&K,  g_K);
    cudaGetSymbolAddress((void**)&V,  g_V);
    cudaGetSymbolAddress((void**)&Vt, g_Vt);
    cudaGetSymbolAddress((void**)&S,  g_S);
    cudaGetSymbolAddress((void**)&WT, g_WT);

    const dim3 blk(256);
    const dim3 tblk(32, 8);
    const int M_proj = BATCH * SEQ;  // 16384

    // 1) Transpose weights: WT[i] = W[i]^T  ([in,out] -> [out,in] K-major)
    {
        dim3 g(DIM / 32, DIM / 32, 1);
        transpose_kernel<<<g, tblk>>>(Wq, WT + 0L * DIM * DIM, DIM, DIM, 0, 0);
        transpose_kernel<<<g, tblk>>>(Wk, WT + 1L * DIM * DIM, DIM, DIM, 0, 0);
        transpose_kernel<<<g, tblk>>>(Wv, WT + 2L * DIM * DIM, DIM, DIM, 0, 0);
    }

    // 2) Projections: Q/K/V[16384,512] = x[16384,512] @ WT[512,512]^T
    {
        dim3 g(DIM / 128, M_proj / 128, 1);
        tc_gemm_kernel<<<g, blk>>>(x, WT + 0L * DIM * DIM, Q, M_proj, DIM, DIM, 0, 0, 0, 1.0f);
        tc_gemm_kernel<<<g, blk>>>(x, WT + 1L * DIM * DIM, K, M_proj, DIM, DIM, 0, 0, 0, 1.0f);
        tc_gemm_kernel<<<g, blk>>>(x, WT + 2L * DIM * DIM, V, M_proj, DIM, DIM, 0, 0, 0, 1.0f);
    }

    // 3) Scores: S[b] = Q[b] @ K[b]^T / sqrt(D)
    {
        const float scale = 0.044194173824159216f;  // 1/sqrt(512)
        dim3 g(SEQ / 128, SEQ / 128, BATCH);
        tc_gemm_kernel<<<g, blk>>>(Q, K, S, SEQ, SEQ, DIM,
                                   (long)SEQ * DIM, (long)SEQ * DIM,
                                   (long)SEQ * SEQ, scale);
    }

    // 4) Softmax rows
    softmax_kernel<<<BATCH * SEQ, blk>>>(S);

    // 5) Transpose V per batch: Vt[b][e][s] = V[b][s][e]
    {
        dim3 g(DIM / 32, SEQ / 32, BATCH);
        transpose_kernel<<<g, tblk>>>(V, Vt, SEQ, DIM,
                                      (long)SEQ * DIM, (long)SEQ * DIM);
    }

    // 6) Output: out[b] = P[b] @ Vt[b]^T   (P [2048,2048], Vt [512,2048])
    {
        dim3 g(DIM / 128, SEQ / 128, BATCH);
        tc_gemm_kernel<<<g, blk>>>(S, Vt, out, SEQ, DIM, SEQ,
                                   (long)SEQ * SEQ, (long)SEQ * DIM,
                                   (long)SEQ * DIM, 1.0f);
    }
}